// round 2
// baseline (speedup 1.0000x reference)
#include <cuda_runtime.h>
#include <cuda_bf16.h>
#include <math_constants.h>

// ---------------------------------------------------------------------------
// SingleAttentionHead: x[8,2048,1024] f32, Wq/Wk/Wv[64,1024] f32
// out[8,2048,64] f32 = causal-softmax( (xWq^T)(xWk^T)^T / 8 ) @ (xWv^T)
// Round 2: packed fma.rn.f32x2 everywhere (2x FLOP per issue slot).
// ---------------------------------------------------------------------------

#define B_   8
#define T_   2048
#define C_   1024
#define H_   64
#define ROWS (B_ * T_)          // 16384

__device__ float g_q[ROWS * H_];
__device__ float g_k[ROWS * H_];
__device__ float g_v[ROWS * H_];

// ---- f32x2 helpers ---------------------------------------------------------
__device__ __forceinline__ void ffma2(unsigned long long& d,
                                      unsigned long long a,
                                      unsigned long long b) {
    asm("fma.rn.f32x2 %0, %1, %2, %0;" : "+l"(d) : "l"(a), "l"(b));
}
__device__ __forceinline__ void fmul2(unsigned long long& d, unsigned long long a) {
    asm("mul.rn.f32x2 %0, %0, %1;" : "+l"(d) : "l"(a));
}
__device__ __forceinline__ float2 unpack2(unsigned long long v) {
    float2 r; asm("mov.b64 {%0, %1}, %2;" : "=f"(r.x), "=f"(r.y) : "l"(v)); return r;
}
__device__ __forceinline__ unsigned long long pack2(float lo, float hi) {
    unsigned long long r; asm("mov.b64 %0, {%1, %2};" : "=l"(r) : "f"(lo), "f"(hi)); return r;
}

// ===========================================================================
// Kernel 1: fused QKV projection, f32x2 packed over k.
// C[16384,192] = X[16384,1024] * W^T. BM=64, BN=192, BK=32, 512 thr, 4x6 tile.
// Xs[row][k] stride 36, Ws[n][k] stride 36 (k contiguous -> v2.b64 loads).
// ===========================================================================
#define XS_ST 36
#define WS_ST 36

__global__ __launch_bounds__(512)
void qkv_proj_kernel(const float* __restrict__ x,
                     const float* __restrict__ Wq,
                     const float* __restrict__ Wk,
                     const float* __restrict__ Wv)
{
    __shared__ float Xs[64 * XS_ST];    // 9216 B
    __shared__ float Ws[192 * WS_ST];   // 27648 B

    const int tid  = threadIdx.x;
    const int row0 = blockIdx.x * 64;

    const int tr4 = (tid >> 5) * 4;   // 0..60 step 4
    const int tc6 = (tid & 31) * 6;   // 0..186 step 6

    unsigned long long acc[4][6];
#pragma unroll
    for (int i = 0; i < 4; i++)
#pragma unroll
        for (int j = 0; j < 6; j++) acc[i][j] = 0ull;

    const int lxr = tid >> 3, lxk = (tid & 7) * 4;   // X loader: 64 rows x 8 float4

    for (int kt = 0; kt < C_ / 32; kt++) {
        const int k0 = kt * 32;

        // load X tile 64x32 (one float4 per thread)
        *(float4*)(Xs + lxr * XS_ST + lxk) =
            *(const float4*)(x + (row0 + lxr) * C_ + k0 + lxk);

        // load W tile 192x32 (three float4 per thread)
#pragma unroll
        for (int i = tid; i < 192 * 8; i += 512) {
            int n = i >> 3, kq = (i & 7) * 4;
            const float* wsrc;
            if (n < 64)       wsrc = Wq + n * C_;
            else if (n < 128) wsrc = Wk + (n - 64) * C_;
            else              wsrc = Wv + (n - 128) * C_;
            *(float4*)(Ws + n * WS_ST + kq) = *(const float4*)(wsrc + k0 + kq);
        }
        __syncthreads();

#pragma unroll
        for (int kk = 0; kk < 32; kk += 4) {
            ulonglong2 a0 = *(const ulonglong2*)(Xs + (tr4 + 0) * XS_ST + kk);
            ulonglong2 a1 = *(const ulonglong2*)(Xs + (tr4 + 1) * XS_ST + kk);
            ulonglong2 a2 = *(const ulonglong2*)(Xs + (tr4 + 2) * XS_ST + kk);
            ulonglong2 a3 = *(const ulonglong2*)(Xs + (tr4 + 3) * XS_ST + kk);
#pragma unroll
            for (int j = 0; j < 6; j++) {
                ulonglong2 b = *(const ulonglong2*)(Ws + (tc6 + j) * WS_ST + kk);
                ffma2(acc[0][j], a0.x, b.x);  ffma2(acc[0][j], a0.y, b.y);
                ffma2(acc[1][j], a1.x, b.x);  ffma2(acc[1][j], a1.y, b.y);
                ffma2(acc[2][j], a2.x, b.x);  ffma2(acc[2][j], a2.y, b.y);
                ffma2(acc[3][j], a3.x, b.x);  ffma2(acc[3][j], a3.y, b.y);
            }
        }
        __syncthreads();
    }

    // epilogue: horizontal add + scatter
#pragma unroll
    for (int i = 0; i < 4; i++) {
        int row = row0 + tr4 + i;
#pragma unroll
        for (int j = 0; j < 6; j++) {
            float2 t = unpack2(acc[i][j]);
            float v = t.x + t.y;
            int n = tc6 + j;
            if (n < 64)       g_q[row * H_ + n]       = v;
            else if (n < 128) g_k[row * H_ + n - 64]  = v;
            else              g_v[row * H_ + n - 128] = v;
        }
    }
}

// ===========================================================================
// Kernel 2: causal flash attention, f32x2 packed.
// Block 256 thr = 8 warps; warp: 8 rows x 64 cols; lane 4x4 micro-tile.
// Qs/Ks/Vs natural [row][d] stride 68. Ps2: P pre-duplicated as f32x2.
// ===========================================================================
#define QS_ST 68
#define KS_ST 68
#define VS_ST 68
#define PS2_ST 128                       // floats per row (64 s * 2 dup)
#define QS_OFF 0
#define KS_OFF (64 * QS_ST)              // 4352
#define VS_OFF (KS_OFF + 64 * KS_ST)     // 8704
#define PS_OFF (VS_OFF + 64 * VS_ST)     // 13056
#define SMEM_FLOATS (PS_OFF + 8 * 8 * PS2_ST)   // 21248
#define ATTN_SMEM_BYTES (SMEM_FLOATS * 4)        // 84992

__global__ __launch_bounds__(256)
void attn_kernel(float* __restrict__ out)
{
    extern __shared__ float sm[];
    float* Qs = sm + QS_OFF;
    float* Ks = sm + KS_OFF;
    float* Vs = sm + VS_OFF;

    const int tid  = threadIdx.x;
    const int w    = tid >> 5;
    const int lane = tid & 31;
    const int rg   = lane >> 4;            // 0..1
    const int cg   = lane & 15;            // 0..15

    float* Psd = sm + PS_OFF + w * (8 * PS2_ST);

    const int qt = 31 - (blockIdx.x >> 3); // heavy tiles first
    const int b  = blockIdx.x & 7;
    const int qrow0 = qt * 64;
    const int gbase = b * T_;

    // load Q tile (float4 per slot)
#pragma unroll
    for (int i = tid; i < 64 * 16; i += 256) {
        int r = i >> 4, d4 = (i & 15) * 4;
        *(float4*)(Qs + r * QS_ST + d4) =
            *(const float4*)(g_q + (gbase + qrow0 + r) * H_ + d4);
    }

    const int rloc  = w * 8 + rg * 4;
    const int qbase = rloc * QS_ST;
    const int col0  = cg * 4;

    unsigned long long o2[4][2];           // packed over d-pairs
    float m_run[4], l_run[4];
#pragma unroll
    for (int i = 0; i < 4; i++) {
        m_run[i] = -CUDART_INF_F;
        l_run[i] = 0.0f;
        o2[i][0] = 0ull; o2[i][1] = 0ull;
    }

    const float scale = 0.125f;

    for (int kt = 0; kt <= qt; kt++) {
        __syncthreads();

        const int srow0 = gbase + kt * 64;
#pragma unroll
        for (int i = tid; i < 64 * 16; i += 256) {
            int r = i >> 4, d4 = (i & 15) * 4;
            *(float4*)(Ks + r * KS_ST + d4) =
                *(const float4*)(g_k + (srow0 + r) * H_ + d4);
            *(float4*)(Vs + r * VS_ST + d4) =
                *(const float4*)(g_v + (srow0 + r) * H_ + d4);
        }
        __syncthreads();

        // ---- S = Q K^T : packed over k-parity
        unsigned long long s2[4][4];
#pragma unroll
        for (int i = 0; i < 4; i++)
#pragma unroll
            for (int j = 0; j < 4; j++) s2[i][j] = 0ull;

#pragma unroll 4
        for (int kk = 0; kk < 64; kk += 4) {
            ulonglong2 a0 = *(const ulonglong2*)(Qs + qbase + kk);
            ulonglong2 a1 = *(const ulonglong2*)(Qs + qbase + QS_ST + kk);
            ulonglong2 a2 = *(const ulonglong2*)(Qs + qbase + 2 * QS_ST + kk);
            ulonglong2 a3 = *(const ulonglong2*)(Qs + qbase + 3 * QS_ST + kk);
#pragma unroll
            for (int j = 0; j < 4; j++) {
                ulonglong2 bk = *(const ulonglong2*)(Ks + (col0 + j) * KS_ST + kk);
                ffma2(s2[0][j], a0.x, bk.x);  ffma2(s2[0][j], a0.y, bk.y);
                ffma2(s2[1][j], a1.x, bk.x);  ffma2(s2[1][j], a1.y, bk.y);
                ffma2(s2[2][j], a2.x, bk.x);  ffma2(s2[2][j], a2.y, bk.y);
                ffma2(s2[3][j], a3.x, bk.x);  ffma2(s2[3][j], a3.y, bk.y);
            }
        }

        const bool diag = (kt == qt);
        float p[4][4];
#pragma unroll
        for (int i = 0; i < 4; i++) {
            float s4[4];
#pragma unroll
            for (int j = 0; j < 4; j++) {
                float2 t = unpack2(s2[i][j]);
                float v = (t.x + t.y) * scale;
                if (diag && (col0 + j > rloc + i)) v = -CUDART_INF_F;
                s4[j] = v;
            }
            float mt = fmaxf(fmaxf(s4[0], s4[1]), fmaxf(s4[2], s4[3]));
#pragma unroll
            for (int off = 8; off >= 1; off >>= 1)
                mt = fmaxf(mt, __shfl_xor_sync(0xffffffffu, mt, off));

            float m_new = fmaxf(m_run[i], mt);
            float alpha = __expf(m_run[i] - m_new);
            float ls = 0.0f;
#pragma unroll
            for (int j = 0; j < 4; j++) {
                p[i][j] = __expf(s4[j] - m_new);
                ls += p[i][j];
            }
#pragma unroll
            for (int off = 8; off >= 1; off >>= 1)
                ls += __shfl_xor_sync(0xffffffffu, ls, off);

            l_run[i] = l_run[i] * alpha + ls;
            m_run[i] = m_new;
            unsigned long long al = pack2(alpha, alpha);
            fmul2(o2[i][0], al);
            fmul2(o2[i][1], al);
        }

        // stage P duplicated as f32x2
#pragma unroll
        for (int i = 0; i < 4; i++)
#pragma unroll
            for (int j = 0; j < 4; j++)
                *(unsigned long long*)(Psd + (rg * 4 + i) * PS2_ST + (col0 + j) * 2)
                    = pack2(p[i][j], p[i][j]);
        __syncwarp();

        // ---- O += P V (p duplicated, v packed over d)
#pragma unroll 4
        for (int ss = 0; ss < 64; ss += 2) {
            ulonglong2 p0 = *(const ulonglong2*)(Psd + (rg * 4 + 0) * PS2_ST + ss * 2);
            ulonglong2 p1 = *(const ulonglong2*)(Psd + (rg * 4 + 1) * PS2_ST + ss * 2);
            ulonglong2 p2 = *(const ulonglong2*)(Psd + (rg * 4 + 2) * PS2_ST + ss * 2);
            ulonglong2 p3 = *(const ulonglong2*)(Psd + (rg * 4 + 3) * PS2_ST + ss * 2);
            ulonglong2 va = *(const ulonglong2*)(Vs + ss * VS_ST + col0);
            ulonglong2 vb = *(const ulonglong2*)(Vs + (ss + 1) * VS_ST + col0);
            ffma2(o2[0][0], p0.x, va.x);  ffma2(o2[0][1], p0.x, va.y);
            ffma2(o2[1][0], p1.x, va.x);  ffma2(o2[1][1], p1.x, va.y);
            ffma2(o2[2][0], p2.x, va.x);  ffma2(o2[2][1], p2.x, va.y);
            ffma2(o2[3][0], p3.x, va.x);  ffma2(o2[3][1], p3.x, va.y);
            ffma2(o2[0][0], p0.y, vb.x);  ffma2(o2[0][1], p0.y, vb.y);
            ffma2(o2[1][0], p1.y, vb.x);  ffma2(o2[1][1], p1.y, vb.y);
            ffma2(o2[2][0], p2.y, vb.x);  ffma2(o2[2][1], p2.y, vb.y);
            ffma2(o2[3][0], p3.y, vb.x);  ffma2(o2[3][1], p3.y, vb.y);
        }
    }

    // normalize + write out
#pragma unroll
    for (int i = 0; i < 4; i++) {
        float inv = 1.0f / l_run[i];
        float2 t0 = unpack2(o2[i][0]);
        float2 t1 = unpack2(o2[i][1]);
        float4 r;
        r.x = t0.x * inv; r.y = t0.y * inv;
        r.z = t1.x * inv; r.w = t1.y * inv;
        int grow = gbase + qrow0 + rloc + i;
        *(float4*)(out + grow * H_ + col0) = r;
    }
}

// ===========================================================================
extern "C" void kernel_launch(void* const* d_in, const int* in_sizes, int n_in,
                              void* d_out, int out_size)
{
    const float* x  = (const float*)d_in[0];
    const float* Wq = (const float*)d_in[1];
    const float* Wk = (const float*)d_in[2];
    const float* Wv = (const float*)d_in[3];
    float* out = (float*)d_out;

    cudaFuncSetAttribute(attn_kernel,
                         cudaFuncAttributeMaxDynamicSharedMemorySize,
                         ATTN_SMEM_BYTES);

    qkv_proj_kernel<<<ROWS / 64, 512>>>(x, Wq, Wk, Wv);
    attn_kernel<<<(T_ / 64) * B_, 256, ATTN_SMEM_BYTES>>>(out);
}

// round 4
// speedup vs baseline: 3.3024x; 3.3024x over previous
#include <cuda_runtime.h>
#include <cuda_bf16.h>
#include <math_constants.h>
#include <cstdint>

// ---------------------------------------------------------------------------
// SingleAttentionHead: x[8,2048,1024] f32, Wq/Wk/Wv[64,1024] f32
// out[8,2048,64] f32 = causal-softmax( (xWq^T)(xWk^T)^T / 8 ) @ (xWv^T)
// R4: QKV via mma.sync bf16 split (HMMA path, base-target safe); attn = R1.
// ---------------------------------------------------------------------------

#define B_   8
#define T_   2048
#define C_   1024
#define H_   64
#define ROWS (B_ * T_)          // 16384
#define NW   192

__device__ float g_q[ROWS * H_];
__device__ float g_k[ROWS * H_];
__device__ float g_v[ROWS * H_];
__device__ __nv_bfloat16 g_whi[NW * C_];
__device__ __nv_bfloat16 g_wlo[NW * C_];

__device__ __forceinline__ uint32_t smem_u32(const void* p) {
    uint32_t a;
    asm("{ .reg .u64 t; cvta.to.shared.u64 t, %1; cvt.u32.u64 %0, t; }"
        : "=r"(a) : "l"(p));
    return a;
}
__device__ __forceinline__ void ldsm_x4(uint32_t& r0, uint32_t& r1,
                                        uint32_t& r2, uint32_t& r3,
                                        uint32_t addr) {
    asm volatile("ldmatrix.sync.aligned.m8n8.x4.shared.b16 {%0,%1,%2,%3}, [%4];"
                 : "=r"(r0), "=r"(r1), "=r"(r2), "=r"(r3) : "r"(addr));
}
__device__ __forceinline__ void mma_bf16(float* d, const uint32_t* a,
                                         uint32_t b0, uint32_t b1) {
    asm volatile(
        "mma.sync.aligned.m16n8k16.row.col.f32.bf16.bf16.f32 "
        "{%0,%1,%2,%3}, {%4,%5,%6,%7}, {%8,%9}, {%0,%1,%2,%3};"
        : "+f"(d[0]), "+f"(d[1]), "+f"(d[2]), "+f"(d[3])
        : "r"(a[0]), "r"(a[1]), "r"(a[2]), "r"(a[3]), "r"(b0), "r"(b1));
}
__device__ __forceinline__ void store_qkv(int row, int n, float v) {
    if (n < 64)       g_q[row * H_ + n]       = v;
    else if (n < 128) g_k[row * H_ + n - 64]  = v;
    else              g_v[row * H_ + n - 128] = v;
}

// ===========================================================================
// Kernel 0: split W into bf16 hi/lo, layout [n][k] (n: 0-63 q, 64-127 k, rest v)
// ===========================================================================
__global__ __launch_bounds__(256)
void wsplit_kernel(const float* __restrict__ Wq,
                   const float* __restrict__ Wk,
                   const float* __restrict__ Wv)
{
    const int n = blockIdx.x;
    const float* src;
    if (n < 64)       src = Wq + n * C_;
    else if (n < 128) src = Wk + (n - 64) * C_;
    else              src = Wv + (n - 128) * C_;
#pragma unroll
    for (int i = 0; i < 4; i++) {
        int k = threadIdx.x + i * 256;
        float v = src[k];
        __nv_bfloat16 hi = __float2bfloat16(v);
        __nv_bfloat16 lo = __float2bfloat16(v - __bfloat162float(hi));
        g_whi[n * C_ + k] = hi;
        g_wlo[n * C_ + k] = lo;
    }
}

// ===========================================================================
// Kernel 1: QKV projection, mma.sync bf16 split (3-term).
// CTA: 64 rows x 192 cols, BK=32. 8 warps: wm in {0,1} (32 rows), wn in 0..3
// (48 cols = 6 n8 tiles). Smem bf16 stride 40 (conflict-free ldmatrix).
// ===========================================================================
#define LDT 40

__global__ __launch_bounds__(256)
void qkv_mma_kernel(const float* __restrict__ x)
{
    __shared__ __nv_bfloat16 Xhi[64 * LDT], Xlo[64 * LDT];
    __shared__ __nv_bfloat16 Whi[NW * LDT], Wlo[NW * LDT];

    const int tid  = threadIdx.x;
    const int wid  = tid >> 5;
    const int lane = tid & 31;
    const int wm   = wid & 1;          // 0..1
    const int wn   = wid >> 1;         // 0..3
    const int row0 = blockIdx.x * 64;

    float acc[2][6][4];
#pragma unroll
    for (int mt = 0; mt < 2; mt++)
#pragma unroll
        for (int nt = 0; nt < 6; nt++)
#pragma unroll
            for (int e = 0; e < 4; e++) acc[mt][nt][e] = 0.0f;

    // ldmatrix lane addressing
    const int lm  = lane & 7;
    const int seg = lane >> 3;
    const int a_row = lm + (seg & 1) * 8;   // A: seg0 m0-7/k0, seg1 m8-15/k0, seg2 m0-7/k8, seg3 m8-15/k8
    const int a_k   = (seg >> 1) * 8;
    const int b_row = lm + (seg >> 1) * 8;  // B: seg0 n0-7/k0, seg1 n0-7/k8, seg2 n8-15/k0, seg3 n8-15/k8
    const int b_k   = (seg & 1) * 8;

    const uint32_t xhi_b = smem_u32(Xhi), xlo_b = smem_u32(Xlo);
    const uint32_t whi_b = smem_u32(Whi), wlo_b = smem_u32(Wlo);

    const int lr  = tid >> 2;          // X loader: row 0..63
    const int lc8 = (tid & 3) * 8;     // col group

    for (int kt = 0; kt < 32; kt++) {
        const int k0 = kt * 32;
        __syncthreads();

        // ---- load + split X tile (64 x 32 f32 -> bf16 hi/lo)
        {
            const float* src = x + (row0 + lr) * C_ + k0 + lc8;
            float4 v0 = *(const float4*)src;
            float4 v1 = *(const float4*)(src + 4);
            float vv[8] = {v0.x, v0.y, v0.z, v0.w, v1.x, v1.y, v1.z, v1.w};
            __nv_bfloat162 hi[4], lo[4];
#pragma unroll
            for (int j = 0; j < 4; j++) {
                __nv_bfloat16 h0 = __float2bfloat16(vv[2 * j]);
                __nv_bfloat16 h1 = __float2bfloat16(vv[2 * j + 1]);
                hi[j] = __nv_bfloat162(h0, h1);
                lo[j] = __nv_bfloat162(
                    __float2bfloat16(vv[2 * j]     - __bfloat162float(h0)),
                    __float2bfloat16(vv[2 * j + 1] - __bfloat162float(h1)));
            }
            *(uint4*)(Xhi + lr * LDT + lc8) = *(uint4*)hi;
            *(uint4*)(Xlo + lr * LDT + lc8) = *(uint4*)lo;
        }
        // ---- copy W tile (192 x 32 bf16 hi/lo)
#pragma unroll
        for (int i = 0; i < 3; i++) {
            int id = tid + i * 256;
            int n  = id >> 2, c8 = (id & 3) * 8;
            *(uint4*)(Whi + n * LDT + c8) = *(const uint4*)(g_whi + n * C_ + k0 + c8);
            *(uint4*)(Wlo + n * LDT + c8) = *(const uint4*)(g_wlo + n * C_ + k0 + c8);
        }
        __syncthreads();

#pragma unroll
        for (int ks = 0; ks < 2; ks++) {
            const int kof = ks * 16;
            uint32_t ahi[2][4], alo[2][4], bhi[3][4], blo[3][4];
#pragma unroll
            for (int mt = 0; mt < 2; mt++) {
                uint32_t off = (uint32_t)((wm * 32 + mt * 16 + a_row) * LDT + kof + a_k) * 2;
                ldsm_x4(ahi[mt][0], ahi[mt][1], ahi[mt][2], ahi[mt][3], xhi_b + off);
                ldsm_x4(alo[mt][0], alo[mt][1], alo[mt][2], alo[mt][3], xlo_b + off);
            }
#pragma unroll
            for (int p = 0; p < 3; p++) {
                uint32_t off = (uint32_t)((wn * 48 + p * 16 + b_row) * LDT + kof + b_k) * 2;
                ldsm_x4(bhi[p][0], bhi[p][1], bhi[p][2], bhi[p][3], whi_b + off);
                ldsm_x4(blo[p][0], blo[p][1], blo[p][2], blo[p][3], wlo_b + off);
            }
            // 3-term split accumulate: hi*hi, hi*lo, lo*hi
#pragma unroll
            for (int mt = 0; mt < 2; mt++)
#pragma unroll
                for (int nt = 0; nt < 6; nt++) {
                    int p = nt >> 1, h = nt & 1;
                    mma_bf16(acc[mt][nt], ahi[mt], bhi[p][2 * h], bhi[p][2 * h + 1]);
                }
#pragma unroll
            for (int mt = 0; mt < 2; mt++)
#pragma unroll
                for (int nt = 0; nt < 6; nt++) {
                    int p = nt >> 1, h = nt & 1;
                    mma_bf16(acc[mt][nt], ahi[mt], blo[p][2 * h], blo[p][2 * h + 1]);
                }
#pragma unroll
            for (int mt = 0; mt < 2; mt++)
#pragma unroll
                for (int nt = 0; nt < 6; nt++) {
                    int p = nt >> 1, h = nt & 1;
                    mma_bf16(acc[mt][nt], alo[mt], bhi[p][2 * h], bhi[p][2 * h + 1]);
                }
        }
    }

    // ---- epilogue: scatter accumulators to g_q / g_k / g_v
#pragma unroll
    for (int mt = 0; mt < 2; mt++) {
        int rbase = row0 + wm * 32 + mt * 16 + (lane >> 2);
#pragma unroll
        for (int nt = 0; nt < 6; nt++) {
            int nbase = wn * 48 + nt * 8 + (lane & 3) * 2;
            store_qkv(rbase,     nbase,     acc[mt][nt][0]);
            store_qkv(rbase,     nbase + 1, acc[mt][nt][1]);
            store_qkv(rbase + 8, nbase,     acc[mt][nt][2]);
            store_qkv(rbase + 8, nbase + 1, acc[mt][nt][3]);
        }
    }
}

// ===========================================================================
// Kernel 2: causal flash attention, fp32 SIMT (R1, known-good 249us).
// ===========================================================================
#define QS_STRIDE 65
#define KT_STRIDE 68
#define VS_STRIDE 68
#define PS_STRIDE 65
#define QS_OFF 0
#define KT_OFF (64 * QS_STRIDE)
#define VS_OFF (KT_OFF + 64 * KT_STRIDE)
#define PS_OFF (VS_OFF + 64 * VS_STRIDE)
#define SMEM_FLOATS (PS_OFF + 8 * 8 * PS_STRIDE)
#define ATTN_SMEM_BYTES (SMEM_FLOATS * 4)

__global__ __launch_bounds__(256)
void attn_kernel(float* __restrict__ out)
{
    extern __shared__ float smf[];
    float* Qs = smf + QS_OFF;
    float* Kt = smf + KT_OFF;
    float* Vs = smf + VS_OFF;

    const int tid  = threadIdx.x;
    const int w    = tid >> 5;
    const int lane = tid & 31;
    const int rg   = lane >> 4;
    const int cg   = lane & 15;

    float* Ps = smf + PS_OFF + w * (8 * PS_STRIDE);

    const int qt = 31 - (blockIdx.x >> 3);
    const int b  = blockIdx.x & 7;
    const int qrow0 = qt * 64;
    const int gbase = b * T_;

    for (int idx = tid; idx < 64 * 64; idx += 256) {
        int r = idx >> 6, d = idx & 63;
        Qs[r * QS_STRIDE + d] = g_q[(gbase + qrow0 + r) * H_ + d];
    }

    const int rloc = w * 8 + rg * 4;
    const int qbase = rloc * QS_STRIDE;

    float o[4][4];
    float m_run[4], l_run[4];
#pragma unroll
    for (int i = 0; i < 4; i++) {
        m_run[i] = -CUDART_INF_F;
        l_run[i] = 0.0f;
#pragma unroll
        for (int j = 0; j < 4; j++) o[i][j] = 0.0f;
    }

    const float scale = 0.125f;
    const int lc_d = tid & 63;
    const int lc_s0 = tid >> 6;

    for (int kt = 0; kt <= qt; kt++) {
        __syncthreads();

        const int srow0 = gbase + kt * 64;
#pragma unroll
        for (int ii = 0; ii < 16; ii++) {
            int s = lc_s0 + ii * 4;
            float kv = g_k[(srow0 + s) * H_ + lc_d];
            Kt[lc_d * KT_STRIDE + s] = kv;
            Vs[s * VS_STRIDE + lc_d] = g_v[(srow0 + s) * H_ + lc_d];
        }
        __syncthreads();

        float s4[4][4];
#pragma unroll
        for (int i = 0; i < 4; i++)
#pragma unroll
            for (int j = 0; j < 4; j++) s4[i][j] = 0.0f;

#pragma unroll 4
        for (int k = 0; k < 64; k++) {
            float4 bk = *(const float4*)(Kt + k * KT_STRIDE + (cg << 2));
            float a0 = Qs[qbase + k];
            float a1 = Qs[qbase + QS_STRIDE + k];
            float a2 = Qs[qbase + 2 * QS_STRIDE + k];
            float a3 = Qs[qbase + 3 * QS_STRIDE + k];
            s4[0][0] += a0 * bk.x; s4[0][1] += a0 * bk.y; s4[0][2] += a0 * bk.z; s4[0][3] += a0 * bk.w;
            s4[1][0] += a1 * bk.x; s4[1][1] += a1 * bk.y; s4[1][2] += a1 * bk.z; s4[1][3] += a1 * bk.w;
            s4[2][0] += a2 * bk.x; s4[2][1] += a2 * bk.y; s4[2][2] += a2 * bk.z; s4[2][3] += a2 * bk.w;
            s4[3][0] += a3 * bk.x; s4[3][1] += a3 * bk.y; s4[3][2] += a3 * bk.z; s4[3][3] += a3 * bk.w;
        }

        const bool diag = (kt == qt);
        float p[4][4];
#pragma unroll
        for (int i = 0; i < 4; i++) {
#pragma unroll
            for (int j = 0; j < 4; j++) {
                float v = s4[i][j] * scale;
                if (diag && ((cg << 2) + j > rloc + i)) v = -CUDART_INF_F;
                s4[i][j] = v;
            }
            float mt = fmaxf(fmaxf(s4[i][0], s4[i][1]), fmaxf(s4[i][2], s4[i][3]));
#pragma unroll
            for (int off = 8; off >= 1; off >>= 1)
                mt = fmaxf(mt, __shfl_xor_sync(0xffffffffu, mt, off));

            float m_new = fmaxf(m_run[i], mt);
            float alpha = __expf(m_run[i] - m_new);
            float ls = 0.0f;
#pragma unroll
            for (int j = 0; j < 4; j++) {
                p[i][j] = __expf(s4[i][j] - m_new);
                ls += p[i][j];
            }
#pragma unroll
            for (int off = 8; off >= 1; off >>= 1)
                ls += __shfl_xor_sync(0xffffffffu, ls, off);

            l_run[i] = l_run[i] * alpha + ls;
            m_run[i] = m_new;
#pragma unroll
            for (int j = 0; j < 4; j++) o[i][j] *= alpha;
        }

#pragma unroll
        for (int i = 0; i < 4; i++)
#pragma unroll
            for (int j = 0; j < 4; j++)
                Ps[(rg * 4 + i) * PS_STRIDE + (cg << 2) + j] = p[i][j];
        __syncwarp();

#pragma unroll 4
        for (int s = 0; s < 64; s++) {
            float4 vv = *(const float4*)(Vs + s * VS_STRIDE + (cg << 2));
            float p0 = Ps[(rg * 4 + 0) * PS_STRIDE + s];
            float p1 = Ps[(rg * 4 + 1) * PS_STRIDE + s];
            float p2 = Ps[(rg * 4 + 2) * PS_STRIDE + s];
            float p3 = Ps[(rg * 4 + 3) * PS_STRIDE + s];
            o[0][0] += p0 * vv.x; o[0][1] += p0 * vv.y; o[0][2] += p0 * vv.z; o[0][3] += p0 * vv.w;
            o[1][0] += p1 * vv.x; o[1][1] += p1 * vv.y; o[1][2] += p1 * vv.z; o[1][3] += p1 * vv.w;
            o[2][0] += p2 * vv.x; o[2][1] += p2 * vv.y; o[2][2] += p2 * vv.z; o[2][3] += p2 * vv.w;
            o[3][0] += p3 * vv.x; o[3][1] += p3 * vv.y; o[3][2] += p3 * vv.z; o[3][3] += p3 * vv.w;
        }
    }

#pragma unroll
    for (int i = 0; i < 4; i++) {
        float inv = 1.0f / l_run[i];
        float4 r;
        r.x = o[i][0] * inv; r.y = o[i][1] * inv;
        r.z = o[i][2] * inv; r.w = o[i][3] * inv;
        int grow = gbase + qrow0 + rloc + i;
        *(float4*)(out + grow * H_ + (cg << 2)) = r;
    }
}

// ===========================================================================
extern "C" void kernel_launch(void* const* d_in, const int* in_sizes, int n_in,
                              void* d_out, int out_size)
{
    const float* x  = (const float*)d_in[0];
    const float* Wq = (const float*)d_in[1];
    const float* Wk = (const float*)d_in[2];
    const float* Wv = (const float*)d_in[3];
    float* out = (float*)d_out;

    cudaFuncSetAttribute(attn_kernel,
                         cudaFuncAttributeMaxDynamicSharedMemorySize,
                         ATTN_SMEM_BYTES);

    wsplit_kernel<<<NW, 256>>>(Wq, Wk, Wv);
    qkv_mma_kernel<<<ROWS / 64, 256>>>(x);
    attn_kernel<<<(T_ / 64) * B_, 256, ATTN_SMEM_BYTES>>>(out);
}

// round 5
// speedup vs baseline: 5.4343x; 1.6455x over previous
#include <cuda_runtime.h>
#include <cuda_bf16.h>
#include <math_constants.h>
#include <cstdint>

// ---------------------------------------------------------------------------
// SingleAttentionHead: x[8,2048,1024] f32, Wq/Wk/Wv[64,1024] f32
// out[8,2048,64] f32 = causal-softmax( (xWq^T)(xWk^T)^T / 8 ) @ (xWv^T)
// R5: both QKV projection AND attention GEMMs on mma.sync bf16 3-term split.
// ---------------------------------------------------------------------------

#define B_   8
#define T_   2048
#define C_   1024
#define H_   64
#define ROWS (B_ * T_)
#define NW   192

// bf16 hi/lo split storage for q (pre-scaled by 0.125), k, v
__device__ __nv_bfloat16 g_qhi[ROWS * H_], g_qlo[ROWS * H_];
__device__ __nv_bfloat16 g_khi[ROWS * H_], g_klo[ROWS * H_];
__device__ __nv_bfloat16 g_vhi[ROWS * H_], g_vlo[ROWS * H_];
__device__ __nv_bfloat16 g_whi[NW * C_],  g_wlo[NW * C_];

// ---------------- helpers ---------------------------------------------------
__device__ __forceinline__ uint32_t smem_u32(const void* p) {
    uint32_t a;
    asm("{ .reg .u64 t; cvta.to.shared.u64 t, %1; cvt.u32.u64 %0, t; }"
        : "=r"(a) : "l"(p));
    return a;
}
__device__ __forceinline__ void ldsm_x4(uint32_t& r0, uint32_t& r1,
                                        uint32_t& r2, uint32_t& r3,
                                        uint32_t addr) {
    asm volatile("ldmatrix.sync.aligned.m8n8.x4.shared.b16 {%0,%1,%2,%3}, [%4];"
                 : "=r"(r0), "=r"(r1), "=r"(r2), "=r"(r3) : "r"(addr));
}
__device__ __forceinline__ void ldsm_x4_t(uint32_t& r0, uint32_t& r1,
                                          uint32_t& r2, uint32_t& r3,
                                          uint32_t addr) {
    asm volatile("ldmatrix.sync.aligned.m8n8.x4.trans.shared.b16 {%0,%1,%2,%3}, [%4];"
                 : "=r"(r0), "=r"(r1), "=r"(r2), "=r"(r3) : "r"(addr));
}
__device__ __forceinline__ void mma_bf16(float* d, const uint32_t* a,
                                         uint32_t b0, uint32_t b1) {
    asm volatile(
        "mma.sync.aligned.m16n8k16.row.col.f32.bf16.bf16.f32 "
        "{%0,%1,%2,%3}, {%4,%5,%6,%7}, {%8,%9}, {%0,%1,%2,%3};"
        : "+f"(d[0]), "+f"(d[1]), "+f"(d[2]), "+f"(d[3])
        : "r"(a[0]), "r"(a[1]), "r"(a[2]), "r"(a[3]), "r"(b0), "r"(b1));
}
// pack two f32 into bf16x2 (lo -> bits[15:0], hi -> bits[31:16])
__device__ __forceinline__ uint32_t pack_bf16x2(float lo, float hi) {
    uint32_t d;
    asm("cvt.rn.bf16x2.f32 %0, %1, %2;" : "=r"(d) : "f"(hi), "f"(lo));
    return d;
}
__device__ __forceinline__ float bf16lo_f(uint32_t v) { return __uint_as_float(v << 16); }
__device__ __forceinline__ float bf16hi_f(uint32_t v) { return __uint_as_float(v & 0xffff0000u); }

__device__ __forceinline__ void store_split(int row, int n, float v) {
    __nv_bfloat16 *dhi, *dlo; int col;
    if (n < 64)       { v *= 0.125f; dhi = g_qhi; dlo = g_qlo; col = n; }
    else if (n < 128) { dhi = g_khi; dlo = g_klo; col = n - 64; }
    else              { dhi = g_vhi; dlo = g_vlo; col = n - 128; }
    __nv_bfloat16 hi = __float2bfloat16(v);
    __nv_bfloat16 lo = __float2bfloat16(v - __bfloat162float(hi));
    dhi[row * H_ + col] = hi;
    dlo[row * H_ + col] = lo;
}

// ===========================================================================
// Kernel 0: split W into bf16 hi/lo, [n][k]
// ===========================================================================
__global__ __launch_bounds__(256)
void wsplit_kernel(const float* __restrict__ Wq,
                   const float* __restrict__ Wk,
                   const float* __restrict__ Wv)
{
    const int n = blockIdx.x;
    const float* src;
    if (n < 64)       src = Wq + n * C_;
    else if (n < 128) src = Wk + (n - 64) * C_;
    else              src = Wv + (n - 128) * C_;
#pragma unroll
    for (int i = 0; i < 4; i++) {
        int k = threadIdx.x + i * 256;
        float v = src[k];
        __nv_bfloat16 hi = __float2bfloat16(v);
        __nv_bfloat16 lo = __float2bfloat16(v - __bfloat162float(hi));
        g_whi[n * C_ + k] = hi;
        g_wlo[n * C_ + k] = lo;
    }
}

// ===========================================================================
// Kernel 1: QKV projection, mma.sync bf16 3-term split (R4 core),
// epilogue writes bf16 hi/lo splits (q pre-scaled by 0.125).
// ===========================================================================
#define LDT 40

__global__ __launch_bounds__(256)
void qkv_mma_kernel(const float* __restrict__ x)
{
    __shared__ __nv_bfloat16 Xhi[64 * LDT], Xlo[64 * LDT];
    __shared__ __nv_bfloat16 Whi[NW * LDT], Wlo[NW * LDT];

    const int tid  = threadIdx.x;
    const int wid  = tid >> 5;
    const int lane = tid & 31;
    const int wm   = wid & 1;
    const int wn   = wid >> 1;
    const int row0 = blockIdx.x * 64;

    float acc[2][6][4];
#pragma unroll
    for (int mt = 0; mt < 2; mt++)
#pragma unroll
        for (int nt = 0; nt < 6; nt++)
#pragma unroll
            for (int e = 0; e < 4; e++) acc[mt][nt][e] = 0.0f;

    const int lm  = lane & 7;
    const int seg = lane >> 3;
    const int a_row = lm + (seg & 1) * 8;
    const int a_k   = (seg >> 1) * 8;
    const int b_row = lm + (seg >> 1) * 8;
    const int b_k   = (seg & 1) * 8;

    const uint32_t xhi_b = smem_u32(Xhi), xlo_b = smem_u32(Xlo);
    const uint32_t whi_b = smem_u32(Whi), wlo_b = smem_u32(Wlo);

    const int lr  = tid >> 2;
    const int lc8 = (tid & 3) * 8;

    for (int kt = 0; kt < 32; kt++) {
        const int k0 = kt * 32;
        __syncthreads();
        {
            const float* src = x + (row0 + lr) * C_ + k0 + lc8;
            float4 v0 = *(const float4*)src;
            float4 v1 = *(const float4*)(src + 4);
            float vv[8] = {v0.x, v0.y, v0.z, v0.w, v1.x, v1.y, v1.z, v1.w};
            __nv_bfloat162 hi[4], lo[4];
#pragma unroll
            for (int j = 0; j < 4; j++) {
                __nv_bfloat16 h0 = __float2bfloat16(vv[2 * j]);
                __nv_bfloat16 h1 = __float2bfloat16(vv[2 * j + 1]);
                hi[j] = __nv_bfloat162(h0, h1);
                lo[j] = __nv_bfloat162(
                    __float2bfloat16(vv[2 * j]     - __bfloat162float(h0)),
                    __float2bfloat16(vv[2 * j + 1] - __bfloat162float(h1)));
            }
            *(uint4*)(Xhi + lr * LDT + lc8) = *(uint4*)hi;
            *(uint4*)(Xlo + lr * LDT + lc8) = *(uint4*)lo;
        }
#pragma unroll
        for (int i = 0; i < 3; i++) {
            int id = tid + i * 256;
            int n  = id >> 2, c8 = (id & 3) * 8;
            *(uint4*)(Whi + n * LDT + c8) = *(const uint4*)(g_whi + n * C_ + k0 + c8);
            *(uint4*)(Wlo + n * LDT + c8) = *(const uint4*)(g_wlo + n * C_ + k0 + c8);
        }
        __syncthreads();

#pragma unroll
        for (int ks = 0; ks < 2; ks++) {
            const int kof = ks * 16;
            uint32_t ahi[2][4], alo[2][4], bhi[3][4], blo[3][4];
#pragma unroll
            for (int mt = 0; mt < 2; mt++) {
                uint32_t off = (uint32_t)((wm * 32 + mt * 16 + a_row) * LDT + kof + a_k) * 2;
                ldsm_x4(ahi[mt][0], ahi[mt][1], ahi[mt][2], ahi[mt][3], xhi_b + off);
                ldsm_x4(alo[mt][0], alo[mt][1], alo[mt][2], alo[mt][3], xlo_b + off);
            }
#pragma unroll
            for (int p = 0; p < 3; p++) {
                uint32_t off = (uint32_t)((wn * 48 + p * 16 + b_row) * LDT + kof + b_k) * 2;
                ldsm_x4(bhi[p][0], bhi[p][1], bhi[p][2], bhi[p][3], whi_b + off);
                ldsm_x4(blo[p][0], blo[p][1], blo[p][2], blo[p][3], wlo_b + off);
            }
#pragma unroll
            for (int mt = 0; mt < 2; mt++)
#pragma unroll
                for (int nt = 0; nt < 6; nt++) {
                    int p = nt >> 1, h = nt & 1;
                    mma_bf16(acc[mt][nt], ahi[mt], bhi[p][2 * h], bhi[p][2 * h + 1]);
                }
#pragma unroll
            for (int mt = 0; mt < 2; mt++)
#pragma unroll
                for (int nt = 0; nt < 6; nt++) {
                    int p = nt >> 1, h = nt & 1;
                    mma_bf16(acc[mt][nt], ahi[mt], blo[p][2 * h], blo[p][2 * h + 1]);
                }
#pragma unroll
            for (int mt = 0; mt < 2; mt++)
#pragma unroll
                for (int nt = 0; nt < 6; nt++) {
                    int p = nt >> 1, h = nt & 1;
                    mma_bf16(acc[mt][nt], alo[mt], bhi[p][2 * h], bhi[p][2 * h + 1]);
                }
        }
    }

#pragma unroll
    for (int mt = 0; mt < 2; mt++) {
        int rbase = row0 + wm * 32 + mt * 16 + (lane >> 2);
#pragma unroll
        for (int nt = 0; nt < 6; nt++) {
            int nbase = wn * 48 + nt * 8 + (lane & 3) * 2;
            store_split(rbase,     nbase,     acc[mt][nt][0]);
            store_split(rbase,     nbase + 1, acc[mt][nt][1]);
            store_split(rbase + 8, nbase,     acc[mt][nt][2]);
            store_split(rbase + 8, nbase + 1, acc[mt][nt][3]);
        }
    }
}

// ===========================================================================
// Kernel 2: causal flash attention on mma.sync, bf16 3-term split.
// Block: 128 thr = 4 warps; q-tile 64 rows; warp = 16-row band x 64 cols.
// k-tiles of 64. P kept in registers (QK accum layout == PV A-frag layout).
// Smem bf16 stride 72 (conflict-free ldmatrix / uint4).
// ===========================================================================
#define ALD 72
#define MATSZ (64 * ALD)                 // 4608 bf16
#define ATTN_SMEM_BYTES (6 * MATSZ * 2)  // 55296 B

__global__ __launch_bounds__(128)
void attn_mma_kernel(float* __restrict__ out)
{
    extern __shared__ __nv_bfloat16 smb[];
    __nv_bfloat16* Qhi = smb;
    __nv_bfloat16* Qlo = smb + MATSZ;
    __nv_bfloat16* Khi = smb + 2 * MATSZ;
    __nv_bfloat16* Klo = smb + 3 * MATSZ;
    __nv_bfloat16* Vhi = smb + 4 * MATSZ;
    __nv_bfloat16* Vlo = smb + 5 * MATSZ;

    const int tid  = threadIdx.x;
    const int wid  = tid >> 5;            // 0..3  (16-row band)
    const int lane = tid & 31;

    const int qt = 31 - (blockIdx.x >> 3);   // heavy tiles first
    const int b  = blockIdx.x & 7;
    const int qrow0 = qt * 64;
    const int gbase = b * T_;

    // loaders
    const int lr  = tid >> 1;              // 0..63
    const int lc8 = (tid & 1) * 8;         // will iterate cols by 16
    // ldmatrix lane addressing
    const int lm  = lane & 7;
    const int seg = lane >> 3;
    const int a_row = lm + (seg & 1) * 8;
    const int a_k   = (seg >> 1) * 8;
    const int b_row = lm + (seg >> 1) * 8;
    const int b_k   = (seg & 1) * 8;
    const int v_srow = lm + (seg & 1) * 8;
    const int v_dcol = (lane >> 4) * 8;

    // load Q hi/lo (64 x 64)
#pragma unroll
    for (int c = 0; c < 4; c++) {
        int col = lc8 + c * 16;
        *(uint4*)(Qhi + lr * ALD + col) =
            *(const uint4*)(g_qhi + (gbase + qrow0 + lr) * H_ + col);
        *(uint4*)(Qlo + lr * ALD + col) =
            *(const uint4*)(g_qlo + (gbase + qrow0 + lr) * H_ + col);
    }

    const uint32_t qhi_b = smem_u32(Qhi), qlo_b = smem_u32(Qlo);
    const uint32_t khi_b = smem_u32(Khi), klo_b = smem_u32(Klo);
    const uint32_t vhi_b = smem_u32(Vhi), vlo_b = smem_u32(Vlo);

    const int r0    = lane >> 2;           // sub-rows r0, r0+8 within band
    const int cpair = (lane & 3) * 2;

    float o[8][4];
    float m_run[2], l_run[2];
#pragma unroll
    for (int t = 0; t < 8; t++)
#pragma unroll
        for (int e = 0; e < 4; e++) o[t][e] = 0.0f;
    m_run[0] = m_run[1] = -CUDART_INF_F;
    l_run[0] = l_run[1] = 0.0f;

    for (int kt = 0; kt <= qt; kt++) {
        __syncthreads();
        const int srow0 = gbase + kt * 64;
#pragma unroll
        for (int c = 0; c < 4; c++) {
            int col = lc8 + c * 16;
            const int gofs = (srow0 + lr) * H_ + col;
            *(uint4*)(Khi + lr * ALD + col) = *(const uint4*)(g_khi + gofs);
            *(uint4*)(Klo + lr * ALD + col) = *(const uint4*)(g_klo + gofs);
            *(uint4*)(Vhi + lr * ALD + col) = *(const uint4*)(g_vhi + gofs);
            *(uint4*)(Vlo + lr * ALD + col) = *(const uint4*)(g_vlo + gofs);
        }
        __syncthreads();

        // ---- S = (Q*0.125) K^T, 3-term split. s[t][e]: 8 n8 tiles.
        float s[8][4];
#pragma unroll
        for (int t = 0; t < 8; t++)
#pragma unroll
            for (int e = 0; e < 4; e++) s[t][e] = 0.0f;

#pragma unroll
        for (int ks = 0; ks < 4; ks++) {
            const int kof = ks * 16;
            uint32_t ah[4], al[4], bh[4][4], bl[4][4];
            {
                uint32_t off = (uint32_t)((wid * 16 + a_row) * ALD + kof + a_k) * 2;
                ldsm_x4(ah[0], ah[1], ah[2], ah[3], qhi_b + off);
                ldsm_x4(al[0], al[1], al[2], al[3], qlo_b + off);
            }
#pragma unroll
            for (int g = 0; g < 4; g++) {
                uint32_t off = (uint32_t)((g * 16 + b_row) * ALD + kof + b_k) * 2;
                ldsm_x4(bh[g][0], bh[g][1], bh[g][2], bh[g][3], khi_b + off);
                ldsm_x4(bl[g][0], bl[g][1], bl[g][2], bl[g][3], klo_b + off);
            }
#pragma unroll
            for (int g = 0; g < 4; g++)
#pragma unroll
                for (int h = 0; h < 2; h++)
                    mma_bf16(s[2 * g + h], ah, bh[g][2 * h], bh[g][2 * h + 1]);
#pragma unroll
            for (int g = 0; g < 4; g++)
#pragma unroll
                for (int h = 0; h < 2; h++)
                    mma_bf16(s[2 * g + h], ah, bl[g][2 * h], bl[g][2 * h + 1]);
#pragma unroll
            for (int g = 0; g < 4; g++)
#pragma unroll
                for (int h = 0; h < 2; h++)
                    mma_bf16(s[2 * g + h], al, bh[g][2 * h], bh[g][2 * h + 1]);
        }

        // ---- causal mask on diagonal tile
        if (kt == qt) {
#pragma unroll
            for (int t = 0; t < 8; t++)
#pragma unroll
                for (int e = 0; e < 4; e++) {
                    int col = t * 8 + cpair + (e & 1);
                    int row = wid * 16 + r0 + (e >> 1) * 8;
                    if (col > row) s[t][e] = -CUDART_INF_F;
                }
        }

        // ---- online softmax (rows i=0 -> regs 0,1; i=1 -> regs 2,3)
        float p_alpha[2];
#pragma unroll
        for (int i = 0; i < 2; i++) {
            float mt = -CUDART_INF_F;
#pragma unroll
            for (int t = 0; t < 8; t++)
                mt = fmaxf(mt, fmaxf(s[t][2 * i], s[t][2 * i + 1]));
            mt = fmaxf(mt, __shfl_xor_sync(0xffffffffu, mt, 1));
            mt = fmaxf(mt, __shfl_xor_sync(0xffffffffu, mt, 2));

            float m_new = fmaxf(m_run[i], mt);
            float alpha = __expf(m_run[i] - m_new);
            float ls = 0.0f;
#pragma unroll
            for (int t = 0; t < 8; t++) {
                s[t][2 * i]     = __expf(s[t][2 * i]     - m_new);
                s[t][2 * i + 1] = __expf(s[t][2 * i + 1] - m_new);
                ls += s[t][2 * i] + s[t][2 * i + 1];
            }
            ls += __shfl_xor_sync(0xffffffffu, ls, 1);
            ls += __shfl_xor_sync(0xffffffffu, ls, 2);

            l_run[i] = l_run[i] * alpha + ls;
            m_run[i] = m_new;
            p_alpha[i] = alpha;
        }
#pragma unroll
        for (int t = 0; t < 8; t++) {
            o[t][0] *= p_alpha[0]; o[t][1] *= p_alpha[0];
            o[t][2] *= p_alpha[1]; o[t][3] *= p_alpha[1];
        }

        // ---- O += P V  (P from regs: tiles (2ks, 2ks+1) form A-frag of step ks)
#pragma unroll
        for (int ks = 0; ks < 4; ks++) {
            uint32_t pa_hi[4], pa_lo[4];
#pragma unroll
            for (int u = 0; u < 4; u++) {
                const float* st = s[2 * ks + (u >> 1)];
                float e0 = st[(u & 1) * 2], e1 = st[(u & 1) * 2 + 1];
                uint32_t hi = pack_bf16x2(e0, e1);
                pa_hi[u] = hi;
                pa_lo[u] = pack_bf16x2(e0 - bf16lo_f(hi), e1 - bf16hi_f(hi));
            }
            uint32_t bvh[4][4], bvl[4][4];
#pragma unroll
            for (int g = 0; g < 4; g++) {
                uint32_t off = (uint32_t)((ks * 16 + v_srow) * ALD + g * 16 + v_dcol) * 2;
                ldsm_x4_t(bvh[g][0], bvh[g][1], bvh[g][2], bvh[g][3], vhi_b + off);
                ldsm_x4_t(bvl[g][0], bvl[g][1], bvl[g][2], bvl[g][3], vlo_b + off);
            }
#pragma unroll
            for (int g = 0; g < 4; g++)
#pragma unroll
                for (int h = 0; h < 2; h++)
                    mma_bf16(o[2 * g + h], pa_hi, bvh[g][2 * h], bvh[g][2 * h + 1]);
#pragma unroll
            for (int g = 0; g < 4; g++)
#pragma unroll
                for (int h = 0; h < 2; h++)
                    mma_bf16(o[2 * g + h], pa_hi, bvl[g][2 * h], bvl[g][2 * h + 1]);
#pragma unroll
            for (int g = 0; g < 4; g++)
#pragma unroll
                for (int h = 0; h < 2; h++)
                    mma_bf16(o[2 * g + h], pa_lo, bvh[g][2 * h], bvh[g][2 * h + 1]);
        }
    }

    // ---- epilogue: normalize + write (float2 per n8 tile per row)
#pragma unroll
    for (int i = 0; i < 2; i++) {
        float inv = 1.0f / l_run[i];
        int grow = gbase + qrow0 + wid * 16 + r0 + i * 8;
#pragma unroll
        for (int t = 0; t < 8; t++) {
            float2 r2;
            r2.x = o[t][2 * i]     * inv;
            r2.y = o[t][2 * i + 1] * inv;
            *(float2*)(out + grow * H_ + t * 8 + cpair) = r2;
        }
    }
}

// ===========================================================================
extern "C" void kernel_launch(void* const* d_in, const int* in_sizes, int n_in,
                              void* d_out, int out_size)
{
    const float* x  = (const float*)d_in[0];
    const float* Wq = (const float*)d_in[1];
    const float* Wk = (const float*)d_in[2];
    const float* Wv = (const float*)d_in[3];
    float* out = (float*)d_out;

    cudaFuncSetAttribute(attn_mma_kernel,
                         cudaFuncAttributeMaxDynamicSharedMemorySize,
                         ATTN_SMEM_BYTES);

    wsplit_kernel<<<NW, 256>>>(Wq, Wk, Wv);
    qkv_mma_kernel<<<ROWS / 64, 256>>>(x);
    attn_mma_kernel<<<(T_ / 64) * B_, 128, ATTN_SMEM_BYTES>>>(out);
}

// round 6
// speedup vs baseline: 6.3762x; 1.1733x over previous
#include <cuda_runtime.h>
#include <cuda_bf16.h>
#include <math_constants.h>
#include <cstdint>

// ---------------------------------------------------------------------------
// SingleAttentionHead: x[8,2048,1024] f32, Wq/Wk/Wv[64,1024] f32
// out[8,2048,64] f32 = causal-softmax( (xWq^T)(xWk^T)^T / 8 ) @ (xWv^T)
// R6: attn gets cp.async double-buffered K/V, Q frags in regs, exp2 domain.
// ---------------------------------------------------------------------------

#define B_   8
#define T_   2048
#define C_   1024
#define H_   64
#define ROWS (B_ * T_)
#define NW   192

// q pre-scaled by 0.125*log2(e) so softmax uses raw ex2
#define QSCALE 0.180336880111386476f

__device__ __nv_bfloat16 g_qhi[ROWS * H_], g_qlo[ROWS * H_];
__device__ __nv_bfloat16 g_khi[ROWS * H_], g_klo[ROWS * H_];
__device__ __nv_bfloat16 g_vhi[ROWS * H_], g_vlo[ROWS * H_];
__device__ __nv_bfloat16 g_whi[NW * C_],  g_wlo[NW * C_];

// ---------------- helpers ---------------------------------------------------
__device__ __forceinline__ uint32_t smem_u32(const void* p) {
    uint32_t a;
    asm("{ .reg .u64 t; cvta.to.shared.u64 t, %1; cvt.u32.u64 %0, t; }"
        : "=r"(a) : "l"(p));
    return a;
}
__device__ __forceinline__ void ldsm_x4(uint32_t& r0, uint32_t& r1,
                                        uint32_t& r2, uint32_t& r3,
                                        uint32_t addr) {
    asm volatile("ldmatrix.sync.aligned.m8n8.x4.shared.b16 {%0,%1,%2,%3}, [%4];"
                 : "=r"(r0), "=r"(r1), "=r"(r2), "=r"(r3) : "r"(addr));
}
__device__ __forceinline__ void ldsm_x4_t(uint32_t& r0, uint32_t& r1,
                                          uint32_t& r2, uint32_t& r3,
                                          uint32_t addr) {
    asm volatile("ldmatrix.sync.aligned.m8n8.x4.trans.shared.b16 {%0,%1,%2,%3}, [%4];"
                 : "=r"(r0), "=r"(r1), "=r"(r2), "=r"(r3) : "r"(addr));
}
__device__ __forceinline__ void mma_bf16(float* d, const uint32_t* a,
                                         uint32_t b0, uint32_t b1) {
    asm volatile(
        "mma.sync.aligned.m16n8k16.row.col.f32.bf16.bf16.f32 "
        "{%0,%1,%2,%3}, {%4,%5,%6,%7}, {%8,%9}, {%0,%1,%2,%3};"
        : "+f"(d[0]), "+f"(d[1]), "+f"(d[2]), "+f"(d[3])
        : "r"(a[0]), "r"(a[1]), "r"(a[2]), "r"(a[3]), "r"(b0), "r"(b1));
}
__device__ __forceinline__ uint32_t pack_bf16x2(float lo, float hi) {
    uint32_t d;
    asm("cvt.rn.bf16x2.f32 %0, %1, %2;" : "=r"(d) : "f"(hi), "f"(lo));
    return d;
}
__device__ __forceinline__ float bf16lo_f(uint32_t v) { return __uint_as_float(v << 16); }
__device__ __forceinline__ float bf16hi_f(uint32_t v) { return __uint_as_float(v & 0xffff0000u); }
__device__ __forceinline__ float ex2(float x) {
    float y; asm("ex2.approx.f32 %0, %1;" : "=f"(y) : "f"(x)); return y;
}
#define CP_ASYNC16(dst, src) \
    asm volatile("cp.async.cg.shared.global [%0], [%1], 16;" :: "r"(dst), "l"(src))
#define CP_COMMIT() asm volatile("cp.async.commit_group;" ::: "memory")
#define CP_WAIT1()  asm volatile("cp.async.wait_group 1;" ::: "memory")
#define CP_WAIT0()  asm volatile("cp.async.wait_group 0;" ::: "memory")

__device__ __forceinline__ void store_split(int row, int n, float v) {
    __nv_bfloat16 *dhi, *dlo; int col;
    if (n < 64)       { v *= QSCALE; dhi = g_qhi; dlo = g_qlo; col = n; }
    else if (n < 128) { dhi = g_khi; dlo = g_klo; col = n - 64; }
    else              { dhi = g_vhi; dlo = g_vlo; col = n - 128; }
    __nv_bfloat16 hi = __float2bfloat16(v);
    __nv_bfloat16 lo = __float2bfloat16(v - __bfloat162float(hi));
    dhi[row * H_ + col] = hi;
    dlo[row * H_ + col] = lo;
}

// ===========================================================================
// Kernel 0: split W into bf16 hi/lo, [n][k]
// ===========================================================================
__global__ __launch_bounds__(256)
void wsplit_kernel(const float* __restrict__ Wq,
                   const float* __restrict__ Wk,
                   const float* __restrict__ Wv)
{
    const int n = blockIdx.x;
    const float* src;
    if (n < 64)       src = Wq + n * C_;
    else if (n < 128) src = Wk + (n - 64) * C_;
    else              src = Wv + (n - 128) * C_;
#pragma unroll
    for (int i = 0; i < 4; i++) {
        int k = threadIdx.x + i * 256;
        float v = src[k];
        __nv_bfloat16 hi = __float2bfloat16(v);
        __nv_bfloat16 lo = __float2bfloat16(v - __bfloat162float(hi));
        g_whi[n * C_ + k] = hi;
        g_wlo[n * C_ + k] = lo;
    }
}

// ===========================================================================
// Kernel 1: QKV projection, mma.sync bf16 3-term split (R4 core).
// ===========================================================================
#define LDT 40

__global__ __launch_bounds__(256)
void qkv_mma_kernel(const float* __restrict__ x)
{
    __shared__ __nv_bfloat16 Xhi[64 * LDT], Xlo[64 * LDT];
    __shared__ __nv_bfloat16 Whi[NW * LDT], Wlo[NW * LDT];

    const int tid  = threadIdx.x;
    const int wid  = tid >> 5;
    const int lane = tid & 31;
    const int wm   = wid & 1;
    const int wn   = wid >> 1;
    const int row0 = blockIdx.x * 64;

    float acc[2][6][4];
#pragma unroll
    for (int mt = 0; mt < 2; mt++)
#pragma unroll
        for (int nt = 0; nt < 6; nt++)
#pragma unroll
            for (int e = 0; e < 4; e++) acc[mt][nt][e] = 0.0f;

    const int lm  = lane & 7;
    const int seg = lane >> 3;
    const int a_row = lm + (seg & 1) * 8;
    const int a_k   = (seg >> 1) * 8;
    const int b_row = lm + (seg >> 1) * 8;
    const int b_k   = (seg & 1) * 8;

    const uint32_t xhi_b = smem_u32(Xhi), xlo_b = smem_u32(Xlo);
    const uint32_t whi_b = smem_u32(Whi), wlo_b = smem_u32(Wlo);

    const int lr  = tid >> 2;
    const int lc8 = (tid & 3) * 8;

    for (int kt = 0; kt < 32; kt++) {
        const int k0 = kt * 32;
        __syncthreads();
        {
            const float* src = x + (row0 + lr) * C_ + k0 + lc8;
            float4 v0 = *(const float4*)src;
            float4 v1 = *(const float4*)(src + 4);
            float vv[8] = {v0.x, v0.y, v0.z, v0.w, v1.x, v1.y, v1.z, v1.w};
            __nv_bfloat162 hi[4], lo[4];
#pragma unroll
            for (int j = 0; j < 4; j++) {
                __nv_bfloat16 h0 = __float2bfloat16(vv[2 * j]);
                __nv_bfloat16 h1 = __float2bfloat16(vv[2 * j + 1]);
                hi[j] = __nv_bfloat162(h0, h1);
                lo[j] = __nv_bfloat162(
                    __float2bfloat16(vv[2 * j]     - __bfloat162float(h0)),
                    __float2bfloat16(vv[2 * j + 1] - __bfloat162float(h1)));
            }
            *(uint4*)(Xhi + lr * LDT + lc8) = *(uint4*)hi;
            *(uint4*)(Xlo + lr * LDT + lc8) = *(uint4*)lo;
        }
#pragma unroll
        for (int i = 0; i < 3; i++) {
            int id = tid + i * 256;
            int n  = id >> 2, c8 = (id & 3) * 8;
            *(uint4*)(Whi + n * LDT + c8) = *(const uint4*)(g_whi + n * C_ + k0 + c8);
            *(uint4*)(Wlo + n * LDT + c8) = *(const uint4*)(g_wlo + n * C_ + k0 + c8);
        }
        __syncthreads();

#pragma unroll
        for (int ks = 0; ks < 2; ks++) {
            const int kof = ks * 16;
            uint32_t ahi[2][4], alo[2][4], bhi[3][4], blo[3][4];
#pragma unroll
            for (int mt = 0; mt < 2; mt++) {
                uint32_t off = (uint32_t)((wm * 32 + mt * 16 + a_row) * LDT + kof + a_k) * 2;
                ldsm_x4(ahi[mt][0], ahi[mt][1], ahi[mt][2], ahi[mt][3], xhi_b + off);
                ldsm_x4(alo[mt][0], alo[mt][1], alo[mt][2], alo[mt][3], xlo_b + off);
            }
#pragma unroll
            for (int p = 0; p < 3; p++) {
                uint32_t off = (uint32_t)((wn * 48 + p * 16 + b_row) * LDT + kof + b_k) * 2;
                ldsm_x4(bhi[p][0], bhi[p][1], bhi[p][2], bhi[p][3], whi_b + off);
                ldsm_x4(blo[p][0], blo[p][1], blo[p][2], blo[p][3], wlo_b + off);
            }
#pragma unroll
            for (int mt = 0; mt < 2; mt++)
#pragma unroll
                for (int nt = 0; nt < 6; nt++) {
                    int p = nt >> 1, h = nt & 1;
                    mma_bf16(acc[mt][nt], ahi[mt], bhi[p][2 * h], bhi[p][2 * h + 1]);
                }
#pragma unroll
            for (int mt = 0; mt < 2; mt++)
#pragma unroll
                for (int nt = 0; nt < 6; nt++) {
                    int p = nt >> 1, h = nt & 1;
                    mma_bf16(acc[mt][nt], ahi[mt], blo[p][2 * h], blo[p][2 * h + 1]);
                }
#pragma unroll
            for (int mt = 0; mt < 2; mt++)
#pragma unroll
                for (int nt = 0; nt < 6; nt++) {
                    int p = nt >> 1, h = nt & 1;
                    mma_bf16(acc[mt][nt], alo[mt], bhi[p][2 * h], bhi[p][2 * h + 1]);
                }
        }
    }

#pragma unroll
    for (int mt = 0; mt < 2; mt++) {
        int rbase = row0 + wm * 32 + mt * 16 + (lane >> 2);
#pragma unroll
        for (int nt = 0; nt < 6; nt++) {
            int nbase = wn * 48 + nt * 8 + (lane & 3) * 2;
            store_split(rbase,     nbase,     acc[mt][nt][0]);
            store_split(rbase,     nbase + 1, acc[mt][nt][1]);
            store_split(rbase + 8, nbase,     acc[mt][nt][2]);
            store_split(rbase + 8, nbase + 1, acc[mt][nt][3]);
        }
    }
}

// ===========================================================================
// Kernel 2: causal flash attention, mma.sync bf16 3-term split.
// cp.async double-buffered K/V; Q fragments live in registers; exp2 domain.
// Smem: 2 bufs x [Khi|Klo|Vhi|Vlo], each 64 x 72 bf16 (ALD=72).
// ===========================================================================
#define ALD 72
#define MATSZ (64 * ALD)                        // bf16 elements per array
#define BUFSZ (4 * MATSZ)                       // one buffer (4 arrays)
#define ATTN_SMEM_BYTES (2 * BUFSZ * 2)         // 73728 B

__global__ __launch_bounds__(128)
void attn_mma_kernel(float* __restrict__ out)
{
    extern __shared__ __nv_bfloat16 smb[];

    const int tid  = threadIdx.x;
    const int wid  = tid >> 5;
    const int lane = tid & 31;

    const int qt = 31 - (blockIdx.x >> 3);
    const int b  = blockIdx.x & 7;
    const int qrow0 = qt * 64;
    const int gbase = b * T_;

    // ldmatrix lane addressing (B operand + trans-V)
    const int lm  = lane & 7;
    const int seg = lane >> 3;
    const int b_row = lm + (seg >> 1) * 8;
    const int b_k   = (seg & 1) * 8;
    const int v_srow = lm + (seg & 1) * 8;
    const int v_dcol = (lane >> 4) * 8;

    const int r0    = lane >> 2;           // sub-row within band
    const int cpair = (lane & 3) * 2;

    // ---- Q fragments straight from gmem (per-lane A-frag addressing)
    uint32_t qh[4][4], ql[4][4];
    {
        const int qrbase = (gbase + qrow0 + wid * 16 + r0) * H_;
#pragma unroll
        for (int ks = 0; ks < 4; ks++) {
            int c0 = ks * 16 + cpair;
            qh[ks][0] = *(const uint32_t*)(g_qhi + qrbase + c0);
            qh[ks][1] = *(const uint32_t*)(g_qhi + qrbase + 8 * H_ + c0);
            qh[ks][2] = *(const uint32_t*)(g_qhi + qrbase + c0 + 8);
            qh[ks][3] = *(const uint32_t*)(g_qhi + qrbase + 8 * H_ + c0 + 8);
            ql[ks][0] = *(const uint32_t*)(g_qlo + qrbase + c0);
            ql[ks][1] = *(const uint32_t*)(g_qlo + qrbase + 8 * H_ + c0);
            ql[ks][2] = *(const uint32_t*)(g_qlo + qrbase + c0 + 8);
            ql[ks][3] = *(const uint32_t*)(g_qlo + qrbase + 8 * H_ + c0 + 8);
        }
    }

    const uint32_t sm_b = smem_u32(smb);

    // cp.async loader: 2048 16B-chunks per tile / 128 thr = 16 per thread
    const __nv_bfloat16* gsrc[4] = {g_khi, g_klo, g_vhi, g_vlo};

    // prologue: prefetch tile 0 into buffer 0
    {
        const int srow0 = gbase;  // kt = 0
#pragma unroll
        for (int i = 0; i < 16; i++) {
            int id  = tid + i * 128;
            int arr = id >> 9;
            int rem = id & 511;
            int r   = rem >> 3, c8 = (rem & 7) * 8;
            uint32_t dst = sm_b + (uint32_t)(arr * MATSZ + r * ALD + c8) * 2;
            CP_ASYNC16(dst, gsrc[arr] + (srow0 + r) * H_ + c8);
        }
        CP_COMMIT();
    }

    float o[8][4];
    float m_run[2], l_run[2];
#pragma unroll
    for (int t = 0; t < 8; t++)
#pragma unroll
        for (int e = 0; e < 4; e++) o[t][e] = 0.0f;
    m_run[0] = m_run[1] = -CUDART_INF_F;
    l_run[0] = l_run[1] = 0.0f;

    for (int kt = 0; kt <= qt; kt++) {
        const uint32_t buf = sm_b + (uint32_t)((kt & 1) * BUFSZ) * 2;

        __syncthreads();   // everyone done reading the buffer we're about to refill

        if (kt < qt) {
            const int srow0 = gbase + (kt + 1) * 64;
            const uint32_t nb = sm_b + (uint32_t)(((kt + 1) & 1) * BUFSZ) * 2;
#pragma unroll
            for (int i = 0; i < 16; i++) {
                int id  = tid + i * 128;
                int arr = id >> 9;
                int rem = id & 511;
                int r   = rem >> 3, c8 = (rem & 7) * 8;
                uint32_t dst = nb + (uint32_t)(arr * MATSZ + r * ALD + c8) * 2;
                CP_ASYNC16(dst, gsrc[arr] + (srow0 + r) * H_ + c8);
            }
            CP_COMMIT();
            CP_WAIT1();    // current tile's group complete
        } else {
            CP_WAIT0();
        }
        __syncthreads();

        const uint32_t khi_b = buf;
        const uint32_t klo_b = buf + (uint32_t)MATSZ * 2;
        const uint32_t vhi_b = buf + (uint32_t)(2 * MATSZ) * 2;
        const uint32_t vlo_b = buf + (uint32_t)(3 * MATSZ) * 2;

        // ---- S = Q K^T (3-term split), Q frags from regs
        float s[8][4];
#pragma unroll
        for (int t = 0; t < 8; t++)
#pragma unroll
            for (int e = 0; e < 4; e++) s[t][e] = 0.0f;

#pragma unroll
        for (int ks = 0; ks < 4; ks++) {
            const int kof = ks * 16;
            uint32_t bh[4][4], bl[4][4];
#pragma unroll
            for (int g = 0; g < 4; g++) {
                uint32_t off = (uint32_t)((g * 16 + b_row) * ALD + kof + b_k) * 2;
                ldsm_x4(bh[g][0], bh[g][1], bh[g][2], bh[g][3], khi_b + off);
                ldsm_x4(bl[g][0], bl[g][1], bl[g][2], bl[g][3], klo_b + off);
            }
#pragma unroll
            for (int g = 0; g < 4; g++)
#pragma unroll
                for (int h = 0; h < 2; h++)
                    mma_bf16(s[2 * g + h], qh[ks], bh[g][2 * h], bh[g][2 * h + 1]);
#pragma unroll
            for (int g = 0; g < 4; g++)
#pragma unroll
                for (int h = 0; h < 2; h++)
                    mma_bf16(s[2 * g + h], qh[ks], bl[g][2 * h], bl[g][2 * h + 1]);
#pragma unroll
            for (int g = 0; g < 4; g++)
#pragma unroll
                for (int h = 0; h < 2; h++)
                    mma_bf16(s[2 * g + h], ql[ks], bh[g][2 * h], bh[g][2 * h + 1]);
        }

        // ---- causal mask on the diagonal tile
        if (kt == qt) {
#pragma unroll
            for (int t = 0; t < 8; t++)
#pragma unroll
                for (int e = 0; e < 4; e++) {
                    int col = t * 8 + cpair + (e & 1);
                    int row = wid * 16 + r0 + (e >> 1) * 8;
                    if (col > row) s[t][e] = -CUDART_INF_F;
                }
        }

        // ---- online softmax (exp2 domain; scale pre-folded into q)
        float p_alpha[2];
#pragma unroll
        for (int i = 0; i < 2; i++) {
            float mt = -CUDART_INF_F;
#pragma unroll
            for (int t = 0; t < 8; t++)
                mt = fmaxf(mt, fmaxf(s[t][2 * i], s[t][2 * i + 1]));
            mt = fmaxf(mt, __shfl_xor_sync(0xffffffffu, mt, 1));
            mt = fmaxf(mt, __shfl_xor_sync(0xffffffffu, mt, 2));

            float m_new = fmaxf(m_run[i], mt);
            float alpha = ex2(m_run[i] - m_new);
            float ls = 0.0f;
#pragma unroll
            for (int t = 0; t < 8; t++) {
                s[t][2 * i]     = ex2(s[t][2 * i]     - m_new);
                s[t][2 * i + 1] = ex2(s[t][2 * i + 1] - m_new);
                ls += s[t][2 * i] + s[t][2 * i + 1];
            }
            ls += __shfl_xor_sync(0xffffffffu, ls, 1);
            ls += __shfl_xor_sync(0xffffffffu, ls, 2);

            l_run[i] = l_run[i] * alpha + ls;
            m_run[i] = m_new;
            p_alpha[i] = alpha;
        }
#pragma unroll
        for (int t = 0; t < 8; t++) {
            o[t][0] *= p_alpha[0]; o[t][1] *= p_alpha[0];
            o[t][2] *= p_alpha[1]; o[t][3] *= p_alpha[1];
        }

        // ---- O += P V (P in regs; split hi/lo)
#pragma unroll
        for (int ks = 0; ks < 4; ks++) {
            uint32_t pa_hi[4], pa_lo[4];
#pragma unroll
            for (int u = 0; u < 4; u++) {
                const float* st = s[2 * ks + (u >> 1)];
                float e0 = st[(u & 1) * 2], e1 = st[(u & 1) * 2 + 1];
                uint32_t hi = pack_bf16x2(e0, e1);
                pa_hi[u] = hi;
                pa_lo[u] = pack_bf16x2(e0 - bf16lo_f(hi), e1 - bf16hi_f(hi));
            }
            uint32_t bvh[4][4], bvl[4][4];
#pragma unroll
            for (int g = 0; g < 4; g++) {
                uint32_t off = (uint32_t)((ks * 16 + v_srow) * ALD + g * 16 + v_dcol) * 2;
                ldsm_x4_t(bvh[g][0], bvh[g][1], bvh[g][2], bvh[g][3], vhi_b + off);
                ldsm_x4_t(bvl[g][0], bvl[g][1], bvl[g][2], bvl[g][3], vlo_b + off);
            }
#pragma unroll
            for (int g = 0; g < 4; g++)
#pragma unroll
                for (int h = 0; h < 2; h++)
                    mma_bf16(o[2 * g + h], pa_hi, bvh[g][2 * h], bvh[g][2 * h + 1]);
#pragma unroll
            for (int g = 0; g < 4; g++)
#pragma unroll
                for (int h = 0; h < 2; h++)
                    mma_bf16(o[2 * g + h], pa_hi, bvl[g][2 * h], bvl[g][2 * h + 1]);
#pragma unroll
            for (int g = 0; g < 4; g++)
#pragma unroll
                for (int h = 0; h < 2; h++)
                    mma_bf16(o[2 * g + h], pa_lo, bvh[g][2 * h], bvh[g][2 * h + 1]);
        }
    }

    // ---- epilogue: normalize + write
#pragma unroll
    for (int i = 0; i < 2; i++) {
        float inv = 1.0f / l_run[i];
        int grow = gbase + qrow0 + wid * 16 + r0 + i * 8;
#pragma unroll
        for (int t = 0; t < 8; t++) {
            float2 r2;
            r2.x = o[t][2 * i]     * inv;
            r2.y = o[t][2 * i + 1] * inv;
            *(float2*)(out + grow * H_ + t * 8 + cpair) = r2;
        }
    }
}

// ===========================================================================
extern "C" void kernel_launch(void* const* d_in, const int* in_sizes, int n_in,
                              void* d_out, int out_size)
{
    const float* x  = (const float*)d_in[0];
    const float* Wq = (const float*)d_in[1];
    const float* Wk = (const float*)d_in[2];
    const float* Wv = (const float*)d_in[3];
    float* out = (float*)d_out;

    cudaFuncSetAttribute(attn_mma_kernel,
                         cudaFuncAttributeMaxDynamicSharedMemorySize,
                         ATTN_SMEM_BYTES);

    wsplit_kernel<<<NW, 256>>>(Wq, Wk, Wv);
    qkv_mma_kernel<<<ROWS / 64, 256>>>(x);
    attn_mma_kernel<<<(T_ / 64) * B_, 128, ATTN_SMEM_BYTES>>>(out);
}